// round 16
// baseline (speedup 1.0000x reference)
#include <cuda_runtime.h>
#include <cuda_fp16.h>

#define SQ 2048
#define HID 1024
#define HEADS 16
#define HD 64
#define BSZ 2
#define BH (BSZ*HEADS)
#define ROWS_TOT (BSZ*SQ)
#define LOG2E 1.44269504f
#define SHF 8.65617025f  /* 6*log2(e); fixed softmax shift, cancels in O/l */

__device__ __half g_xh[ROWS_TOT*HID];
__device__ __half g_wt[4*HID*HID];     // W^T [n][k] fp16 (mod/scale folded), 4 mats
__device__ __half g_q[BH*SQ*HD];       // mod*0.125 folded
__device__ __half g_k[BH*SQ*HD];       // mod folded
__device__ __half g_v[BH*SQ*HD];       // mod folded
__device__ __half g_vt[BH*HD*SQ];      // rolled V transposed [bh][d][n]
__device__ __half g_att[ROWS_TOT*HID];
__device__ float g_mod[HID];
__device__ float g_cs[SQ];
__device__ float g_sn[SQ];

__device__ __forceinline__ unsigned su(const void* p) {
    return (unsigned)__cvta_generic_to_shared(p);
}
__device__ __forceinline__ float ex2(float x) {
    float y;
    asm("ex2.approx.ftz.f32 %0, %1;" : "=f"(y) : "f"(x));
    return y;
}
__device__ __forceinline__ unsigned pk(float a, float b) {
    __half2 h = __floats2half2_rn(a, b);
    return *(unsigned*)&h;
}

#define LDSM4(R0,R1,R2,R3,A)                                                    \
    asm volatile("ldmatrix.sync.aligned.m8n8.x4.shared.b16 {%0,%1,%2,%3},[%4];" \
                 : "=r"(R0), "=r"(R1), "=r"(R2), "=r"(R3) : "r"(A))
#define HMMA(D,A0,A1,A2,A3,B0,B1)                                               \
    asm volatile("mma.sync.aligned.m16n8k16.row.col.f32.f16.f16.f32 "           \
                 "{%0,%1,%2,%3},{%4,%5,%6,%7},{%8,%9},{%0,%1,%2,%3};"           \
                 : "+f"(D[0]), "+f"(D[1]), "+f"(D[2]), "+f"(D[3])               \
                 : "r"(A0), "r"(A1), "r"(A2), "r"(A3), "r"(B0), "r"(B1))
#define CP16(D,S) asm volatile("cp.async.cg.shared.global [%0],[%1],16;" :: "r"(D), "l"(S))
#define CPC()     asm volatile("cp.async.commit_group;")

// ---------------------------------------------------------------- prep
__global__ void prep_kernel(const float* __restrict__ phase,
                            const float* __restrict__ amp) {
    int i = blockIdx.x * 256 + threadIdx.x;
    if (i < HID) g_mod[i] = cosf(phase[i]) * amp[i];
    if (i < SQ) {
        float a = 6.283185307179586f * (float)i / (float)SQ;
        g_cs[i] = cosf(a);
        g_sn[i] = sinf(a);
    }
}

__global__ void convert_x(const float* __restrict__ x) {
    int i = (blockIdx.x * 256 + threadIdx.x) * 8;
    float4 f0 = *(const float4*)(x + i);
    float4 f1 = *(const float4*)(x + i + 4);
    __half2* o = (__half2*)(g_xh + i);
    o[0] = __floats2half2_rn(f0.x, f0.y);
    o[1] = __floats2half2_rn(f0.z, f0.w);
    o[2] = __floats2half2_rn(f1.x, f1.y);
    o[3] = __floats2half2_rn(f1.z, f1.w);
}

// transpose W -> fp16 [n][k], with mod (q/k/v) and 1/8 (q) folded into row n.
__global__ void transpose_w(const float* __restrict__ Wq, const float* __restrict__ Wk,
                            const float* __restrict__ Wv, const float* __restrict__ Wo) {
    __shared__ float t[32][33];
    int z = blockIdx.z;
    const float* W = (z == 0) ? Wq : (z == 1) ? Wk : (z == 2) ? Wv : Wo;
    int n0 = blockIdx.x * 32, k0 = blockIdx.y * 32;
    int tx = threadIdx.x, ty = threadIdx.y;
#pragma unroll
    for (int i = 0; i < 4; i++)
        t[ty + i * 8][tx] = W[(size_t)(k0 + ty + i * 8) * HID + n0 + tx];
    __syncthreads();
    __half* dst = g_wt + (size_t)z * HID * HID;
#pragma unroll
    for (int i = 0; i < 4; i++) {
        int n = n0 + ty + i * 8;
        float sc = (z == 3) ? 1.0f : g_mod[n] * ((z == 0) ? 0.125f : 1.0f);
        dst[(size_t)n * HID + k0 + tx] = __float2half_rn(t[tx][ty + i * 8] * sc);
    }
}

__global__ __launch_bounds__(256) void roll_t_kernel() {
    __shared__ __half ts[65][72];
    int n0 = blockIdx.x * 64, bh = blockIdx.y, tid = threadIdx.x;
    int rr = tid >> 2, seg = (tid & 3) * 16;
    const __half* src = g_v + ((size_t)bh * SQ + n0 + rr) * HD + seg;
    *(uint4*)&ts[rr][seg] = *(const uint4*)src;
    *(uint4*)&ts[rr][seg + 8] = *(const uint4*)(src + 8);
    if (tid < 4) {
        int nz = (n0 + 64) & (SQ - 1);
        const __half* s2 = g_v + ((size_t)bh * SQ + nz) * HD + tid * 16;
        *(uint4*)&ts[64][tid * 16] = *(const uint4*)s2;
        *(uint4*)&ts[64][tid * 16 + 8] = *(const uint4*)(s2 + 8);
    }
    __syncthreads();
    int d = tid >> 2, ns = (tid & 3) * 16;
    const float R = 0.7071067811865476f;
    __half2 ov[8];
#pragma unroll
    for (int i = 0; i < 8; i++) {
        int n = ns + 2 * i;
        float a = __half2float(ts[n][d]);
        float b = __half2float(ts[n + 1][d]);
        float c = __half2float(ts[n + 2][d]);
        ov[i] = __floats2half2_rn((a + b) * R, (b + c) * R);
    }
    __half* dst = g_vt + ((size_t)bh * HD + d) * SQ + n0 + ns;
    *(uint4*)dst = *(uint4*)&ov[0];
    *(uint4*)(dst + 8) = *(uint4*)&ov[4];
}

// ---------------------------------------------------------------- fp16 GEMM core v5b
// 512 thr = 16 warps (4m x 4n), block 128x128, warp m32 x n32.
// kblock 64 (4 k16-steps per stage, 16 stages), double-buffered cp.async.
// Per stage each of 256 loader threads covers a 32-half (64B) segment = 4 x CP16.
#define GLDA 72
#define GSTG (128*GLDA)

__device__ __forceinline__ void gemm_core(const __half* Arow0, const __half* Brow0,
                                          float (&acc)[2][4][4]) {
    extern __shared__ __half sm[];
    __half* As = sm;               // [2][128][72]
    __half* Bs = sm + 2 * GSTG;    // [2][128][72]
    int tid = threadIdx.x, lane = tid & 31, w = tid >> 5;
    int wm = w >> 2, wn = w & 3;

    // threads 0..255 load A, 256..511 load B: row = t>>1, 32-half segment
    int t = tid & 255;
    int lrow = t >> 1, lseg = (t & 1) * 32;
    const __half* src = (tid < 256) ? (Arow0 + (size_t)lrow * HID + lseg)
                                    : (Brow0 + (size_t)lrow * HID + lseg);
    unsigned dstb = (tid < 256) ? su(As + lrow * GLDA + lseg)
                                : su(Bs + lrow * GLDA + lseg);

#pragma unroll
    for (int q = 0; q < 4; q++)
        CP16(dstb + q * 16, src + q * 8);
    CPC();

    int arow = wm * 32 + (lane & 15);
    int brow = wn * 32 + (lane & 15);
    int coff = (lane >> 4) * 8;

    for (int st = 0; st < 16; st++) {
        int buf = st & 1;
        if (st < 15) {
            unsigned nb = (unsigned)((st + 1) & 1);
            const __half* s2 = src + (st + 1) * 64;
#pragma unroll
            for (int q = 0; q < 4; q++)
                CP16(dstb + nb * GSTG * 2 + q * 16, s2 + q * 8);
            CPC();
            asm volatile("cp.async.wait_group 1;");
        } else {
            asm volatile("cp.async.wait_group 0;");
        }
        __syncthreads();
        const __half* Ac = As + buf * GSTG;
        const __half* Bc = Bs + buf * GSTG;
#pragma unroll
        for (int kk = 0; kk < 4; kk++) {
            unsigned au[2][4], bu[2][4];
#pragma unroll
            for (int i = 0; i < 2; i++)
                LDSM4(au[i][0], au[i][1], au[i][2], au[i][3],
                      su(Ac + (arow + i * 16) * GLDA + kk * 16 + coff));
#pragma unroll
            for (int jp = 0; jp < 2; jp++)
                LDSM4(bu[jp][0], bu[jp][1], bu[jp][2], bu[jp][3],
                      su(Bc + (brow + jp * 16) * GLDA + kk * 16 + coff));
#pragma unroll
            for (int i = 0; i < 2; i++)
#pragma unroll
                for (int j = 0; j < 4; j++)
                    HMMA(acc[i][j], au[i][0], au[i][1], au[i][2], au[i][3],
                         bu[j >> 1][j & 1], bu[j >> 1][2 + (j & 1)]);
        }
        __syncthreads();
    }
}

#define GS_BYTES (4*GSTG*2)

__global__ __launch_bounds__(512, 2) void qkv_gemm() {
    int mode = blockIdx.z;
    float acc[2][4][4];
#pragma unroll
    for (int i = 0; i < 2; i++)
#pragma unroll
        for (int j = 0; j < 4; j++)
#pragma unroll
            for (int e = 0; e < 4; e++) acc[i][j][e] = 0.f;
    int bm = blockIdx.y, bn = blockIdx.x;
    gemm_core(g_xh + (size_t)bm * 128 * HID,
              g_wt + (size_t)mode * HID * HID + (size_t)bn * 128 * HID, acc);

    __half* dst = (mode == 0) ? g_q : (mode == 1) ? g_k : g_v;
    int tid = threadIdx.x, lane = tid & 31, w = tid >> 5;
    int wm = w >> 2, wn = w & 3, r = lane >> 2, c = lane & 3;
#pragma unroll
    for (int i = 0; i < 2; i++) {
#pragma unroll
        for (int ro = 0; ro < 2; ro++) {
            int grow = bm * 128 + wm * 32 + i * 16 + r + ro * 8;
            int bb = grow >> 11, ss = grow & 2047;
#pragma unroll
            for (int j = 0; j < 4; j++) {
                int col = bn * 128 + wn * 32 + j * 8 + 2 * c;
                int hh = col >> 6, dd = col & 63;
                __half2 v = __floats2half2_rn(acc[i][j][ro * 2],
                                              acc[i][j][ro * 2 + 1]);
                *(__half2*)&dst[(((size_t)(bb * HEADS + hh) * SQ + ss) * HD + dd)] = v;
            }
        }
    }
}

__global__ __launch_bounds__(512, 2) void out_gemm(float* __restrict__ C) {
    float acc[2][4][4];
#pragma unroll
    for (int i = 0; i < 2; i++)
#pragma unroll
        for (int j = 0; j < 4; j++)
#pragma unroll
            for (int e = 0; e < 4; e++) acc[i][j][e] = 0.f;
    int bm = blockIdx.y, bn = blockIdx.x;
    gemm_core(g_att + (size_t)bm * 128 * HID,
              g_wt + (size_t)3 * HID * HID + (size_t)bn * 128 * HID, acc);

    int tid = threadIdx.x, lane = tid & 31, w = tid >> 5;
    int wm = w >> 2, wn = w & 3, r = lane >> 2, c = lane & 3;
#pragma unroll
    for (int i = 0; i < 2; i++) {
#pragma unroll
        for (int ro = 0; ro < 2; ro++) {
            int grow = bm * 128 + wm * 32 + i * 16 + r + ro * 8;
#pragma unroll
            for (int j = 0; j < 4; j++) {
                int col = bn * 128 + wn * 32 + j * 8 + 2 * c;
                float2 v = {acc[i][j][ro * 2], acc[i][j][ro * 2 + 1]};
                *(float2*)&C[(size_t)grow * HID + col] = v;
            }
        }
    }
}

// ---------------------------------------------------------------- flash attention fp16 (R14-proven)
// 8 warps, warp owns rows [w*16,w*16+16), N-tile 64, cp.async double-buffered,
// one sync per iteration.
#define AQ 0
#define AK (128*72)
#define AV (AK + 2*64*72)
#define ATRIG (AV + 2*64*72)
#define ATT_BYTES (ATRIG*2 + 2*128*4)

__global__ __launch_bounds__(256, 2) void attn_kernel() {
    extern __shared__ __half sma[];
    __half* Qs = sma + AQ;
    __half* Ks = sma + AK;
    __half* Vts = sma + AV;
    float* cjs = (float*)(sma + ATRIG);   // [2][64]
    float* sjs = cjs + 128;               // [2][64]

    int m0 = blockIdx.x * 128, h = blockIdx.y, b = blockIdx.z;
    int bh = b * HEADS + h;
    const __half* Qg = g_q + (size_t)bh * SQ * HD;
    const __half* Kg = g_k + (size_t)bh * SQ * HD;
    const __half* Vg = g_vt + (size_t)bh * HD * SQ;

    int tid = threadIdx.x, lane = tid & 31, w = tid >> 5;
    int r = lane >> 2, c = lane & 3;
    int krow = tid >> 2, kseg = (tid & 3) * 16;

    {   // Q tile -> smem
        int row = tid >> 1, seg = (tid & 1) * 32;
        const uint4* s = (const uint4*)(Qg + (size_t)(m0 + row) * HD + seg);
        uint4* d = (uint4*)(Qs + row * 72 + seg);
        d[0] = s[0]; d[1] = s[1]; d[2] = s[2]; d[3] = s[3];
    }
    // prologue: async load tile 0 into buffer 0
    {
        CP16(su(Ks + krow * 72 + kseg), Kg + (size_t)krow * HD + kseg);
        CP16(su(Ks + krow * 72 + kseg + 8), Kg + (size_t)krow * HD + kseg + 8);
        CP16(su(Vts + krow * 72 + kseg), Vg + (size_t)krow * SQ + kseg);
        CP16(su(Vts + krow * 72 + kseg + 8), Vg + (size_t)krow * SQ + kseg + 8);
        if (tid < 16) CP16(su(cjs + tid * 4), g_cs + tid * 4);
        else if (tid < 32) CP16(su(sjs + (tid - 16) * 4), g_sn + (tid - 16) * 4);
        CPC();
    }
    asm volatile("cp.async.wait_group 0;");
    __syncthreads();   // Q + buffer0 ready

    unsigned qa[4][4];
#pragma unroll
    for (int kk = 0; kk < 4; kk++)
        LDSM4(qa[kk][0], qa[kk][1], qa[kk][2], qa[kk][3],
              su(Qs + (w * 16 + (lane & 15)) * 72 + kk * 16 + (lane >> 4) * 8));

    float cm0, sm0, cm1, sm1;  // premultiplied by LOG2E
    {
        int row = m0 + w * 16 + r;
        cm0 = g_cs[row] * LOG2E; sm0 = g_sn[row] * LOG2E;
        cm1 = g_cs[row + 8] * LOG2E; sm1 = g_sn[row + 8] * LOG2E;
    }
    float l0 = 0.f, l1 = 0.f;
    float o[8][4];
#pragma unroll
    for (int j = 0; j < 8; j++)
#pragma unroll
        for (int e = 0; e < 4; e++) o[j][e] = 0.f;

    for (int it = 0; it < 32; it++) {
        int buf = it & 1;
        const __half* Kc = Ks + buf * 4608;
        const __half* Vc = Vts + buf * 4608;
        const float* cjb = cjs + buf * 64;
        const float* sjb = sjs + buf * 64;

        if (it < 31) {   // prefetch next tile into other buffer
            int nb = buf ^ 1;
            int n1 = (it + 1) * 64;
            CP16(su(Ks + nb * 4608 + krow * 72 + kseg), Kg + (size_t)(n1 + krow) * HD + kseg);
            CP16(su(Ks + nb * 4608 + krow * 72 + kseg + 8), Kg + (size_t)(n1 + krow) * HD + kseg + 8);
            CP16(su(Vts + nb * 4608 + krow * 72 + kseg), Vg + (size_t)krow * SQ + n1 + kseg);
            CP16(su(Vts + nb * 4608 + krow * 72 + kseg + 8), Vg + (size_t)krow * SQ + n1 + kseg + 8);
            if (tid < 16) CP16(su(cjs + nb * 64 + tid * 4), g_cs + n1 + tid * 4);
            else if (tid < 32) CP16(su(sjs + nb * 64 + (tid - 16) * 4), g_sn + n1 + (tid - 16) * 4);
            CPC();
        }

        // S = Q K^T (m16 x n64)
        float s[8][4];
#pragma unroll
        for (int j = 0; j < 8; j++)
#pragma unroll
            for (int e = 0; e < 4; e++) s[j][e] = 0.f;
#pragma unroll
        for (int kk = 0; kk < 4; kk++) {
#pragma unroll
            for (int jp = 0; jp < 4; jp++) {
                unsigned b0, b1, b2, b3;
                LDSM4(b0, b1, b2, b3,
                      su(Kc + (jp * 16 + (lane & 15)) * 72 + kk * 16 + (lane >> 4) * 8));
                HMMA(s[2 * jp], qa[kk][0], qa[kk][1], qa[kk][2], qa[kk][3], b0, b2);
                HMMA(s[2 * jp + 1], qa[kk][0], qa[kk][1], qa[kk][2], qa[kk][3], b1, b3);
            }
        }

        // interference + exp2(s - SHF) + l accumulation, pack to fp16 A-frags
        unsigned pf[4][4];
#pragma unroll
        for (int j = 0; j < 8; j++) {
            float2 cj = *(float2*)&cjb[j * 8 + 2 * c];
            float2 sj = *(float2*)&sjb[j * 8 + 2 * c];
            float w00 = cm0 * cj.x + sm0 * sj.x;
            float w01 = cm0 * cj.y + sm0 * sj.y;
            float w10 = cm1 * cj.x + sm1 * sj.x;
            float w11 = cm1 * cj.y + sm1 * sj.y;
            s[j][0] = ex2(fmaf(s[j][0], w00, -SHF));
            s[j][1] = ex2(fmaf(s[j][1], w01, -SHF));
            s[j][2] = ex2(fmaf(s[j][2], w10, -SHF));
            s[j][3] = ex2(fmaf(s[j][3], w11, -SHF));
            l0 += s[j][0] + s[j][1];
            l1 += s[j][2] + s[j][3];
        }
#pragma unroll
        for (int kk = 0; kk < 4; kk++) {
            pf[kk][0] = pk(s[2 * kk][0], s[2 * kk][1]);
            pf[kk][1] = pk(s[2 * kk][2], s[2 * kk][3]);
            pf[kk][2] = pk(s[2 * kk + 1][0], s[2 * kk + 1][1]);
            pf[kk][3] = pk(s[2 * kk + 1][2], s[2 * kk + 1][3]);
        }

        // O += P @ V' (m16 x d64, k=n64)
#pragma unroll
        for (int kk = 0; kk < 4; kk++) {
#pragma unroll
            for (int jp = 0; jp < 4; jp++) {
                unsigned b0, b1, b2, b3;
                LDSM4(b0, b1, b2, b3,
                      su(Vc + (jp * 16 + (lane & 15)) * 72 + kk * 16 + (lane >> 4) * 8));
                HMMA(o[2 * jp], pf[kk][0], pf[kk][1], pf[kk][2], pf[kk][3], b0, b2);
                HMMA(o[2 * jp + 1], pf[kk][0], pf[kk][1], pf[kk][2], pf[kk][3], b1, b3);
            }
        }

        if (it < 31) {   // next buffer ready + all warps done with it
            asm volatile("cp.async.wait_group 0;");
            __syncthreads();
        }
    }

    l0 += __shfl_xor_sync(0xffffffffu, l0, 1);
    l0 += __shfl_xor_sync(0xffffffffu, l0, 2);
    l1 += __shfl_xor_sync(0xffffffffu, l1, 1);
    l1 += __shfl_xor_sync(0xffffffffu, l1, 2);
    float i0 = 1.0f / l0, i1 = 1.0f / l1;

    int row0 = b * SQ + m0 + w * 16 + r;
#pragma unroll
    for (int j = 0; j < 8; j++) {
        int col = h * HD + j * 8 + 2 * c;
        *(__half2*)&g_att[(size_t)row0 * HID + col] =
            __floats2half2_rn(o[j][0] * i0, o[j][1] * i0);
        *(__half2*)&g_att[(size_t)(row0 + 8) * HID + col] =
            __floats2half2_rn(o[j][2] * i1, o[j][3] * i1);
    }
}

// ---------------------------------------------------------------- launch
extern "C" void kernel_launch(void* const* d_in, const int* in_sizes, int n_in,
                              void* d_out, int out_size) {
    const float* x     = (const float*)d_in[0];
    const float* Wq    = (const float*)d_in[1];
    const float* Wk    = (const float*)d_in[2];
    const float* Wv    = (const float*)d_in[3];
    const float* Wo    = (const float*)d_in[4];
    const float* phase = (const float*)d_in[5];
    const float* amp   = (const float*)d_in[6];
    float* out = (float*)d_out;

    cudaFuncSetAttribute(qkv_gemm, cudaFuncAttributeMaxDynamicSharedMemorySize, GS_BYTES);
    cudaFuncSetAttribute(out_gemm, cudaFuncAttributeMaxDynamicSharedMemorySize, GS_BYTES);
    cudaFuncSetAttribute(attn_kernel, cudaFuncAttributeMaxDynamicSharedMemorySize, ATT_BYTES);

    prep_kernel<<<8, 256>>>(phase, amp);
    convert_x<<<ROWS_TOT * HID / (256 * 8), 256>>>(x);
    transpose_w<<<dim3(32, 32, 4), dim3(32, 8)>>>(Wq, Wk, Wv, Wo);
    qkv_gemm<<<dim3(8, 32, 3), 512, GS_BYTES>>>();
    roll_t_kernel<<<dim3(SQ / 64, BH), 256>>>();
    attn_kernel<<<dim3(16, 16, 2), 256, ATT_BYTES>>>();
    out_gemm<<<dim3(8, 32), 512, GS_BYTES>>>(out);
}

// round 17
// speedup vs baseline: 1.2036x; 1.2036x over previous
#include <cuda_runtime.h>
#include <cuda_fp16.h>

#define SQ 2048
#define HID 1024
#define HEADS 16
#define HD 64
#define BSZ 2
#define BH (BSZ*HEADS)
#define ROWS_TOT (BSZ*SQ)
#define LOG2E 1.44269504f
#define SHF 8.65617025f  /* 6*log2(e); fixed softmax shift, cancels in O/l */

__device__ __half g_xh[ROWS_TOT*HID];
__device__ __half g_wt[4*HID*HID];     // W^T [n][k] fp16 (mod/scale folded), 4 mats
__device__ __half g_q[BH*SQ*HD];       // mod*0.125 folded
__device__ __half g_k[BH*SQ*HD];       // mod folded
__device__ __half g_v[BH*SQ*HD];       // mod folded
__device__ __half g_vt[BH*HD*SQ];      // rolled V transposed [bh][d][n]
__device__ __half g_att[ROWS_TOT*HID];
__device__ float g_mod[HID];
__device__ float g_cs[SQ];
__device__ float g_sn[SQ];

__device__ __forceinline__ unsigned su(const void* p) {
    return (unsigned)__cvta_generic_to_shared(p);
}
__device__ __forceinline__ float ex2(float x) {
    float y;
    asm("ex2.approx.ftz.f32 %0, %1;" : "=f"(y) : "f"(x));
    return y;
}
__device__ __forceinline__ unsigned pk(float a, float b) {
    __half2 h = __floats2half2_rn(a, b);
    return *(unsigned*)&h;
}

#define LDSM4(R0,R1,R2,R3,A)                                                    \
    asm volatile("ldmatrix.sync.aligned.m8n8.x4.shared.b16 {%0,%1,%2,%3},[%4];" \
                 : "=r"(R0), "=r"(R1), "=r"(R2), "=r"(R3) : "r"(A))
#define HMMA(D,A0,A1,A2,A3,B0,B1)                                               \
    asm volatile("mma.sync.aligned.m16n8k16.row.col.f32.f16.f16.f32 "           \
                 "{%0,%1,%2,%3},{%4,%5,%6,%7},{%8,%9},{%0,%1,%2,%3};"           \
                 : "+f"(D[0]), "+f"(D[1]), "+f"(D[2]), "+f"(D[3])               \
                 : "r"(A0), "r"(A1), "r"(A2), "r"(A3), "r"(B0), "r"(B1))
#define CP16(D,S) asm volatile("cp.async.cg.shared.global [%0],[%1],16;" :: "r"(D), "l"(S))
#define CPC()     asm volatile("cp.async.commit_group;")

// ---------------------------------------------------------------- prep
__global__ void prep_kernel(const float* __restrict__ phase,
                            const float* __restrict__ amp) {
    int i = blockIdx.x * 256 + threadIdx.x;
    if (i < HID) g_mod[i] = cosf(phase[i]) * amp[i];
    if (i < SQ) {
        float a = 6.283185307179586f * (float)i / (float)SQ;
        g_cs[i] = cosf(a);
        g_sn[i] = sinf(a);
    }
}

__global__ void convert_x(const float* __restrict__ x) {
    int i = (blockIdx.x * 256 + threadIdx.x) * 8;
    float4 f0 = *(const float4*)(x + i);
    float4 f1 = *(const float4*)(x + i + 4);
    __half2* o = (__half2*)(g_xh + i);
    o[0] = __floats2half2_rn(f0.x, f0.y);
    o[1] = __floats2half2_rn(f0.z, f0.w);
    o[2] = __floats2half2_rn(f1.x, f1.y);
    o[3] = __floats2half2_rn(f1.z, f1.w);
}

// transpose W -> fp16 [n][k], with mod (q/k/v) and 1/8 (q) folded into row n.
__global__ void transpose_w(const float* __restrict__ Wq, const float* __restrict__ Wk,
                            const float* __restrict__ Wv, const float* __restrict__ Wo) {
    __shared__ float t[32][33];
    int z = blockIdx.z;
    const float* W = (z == 0) ? Wq : (z == 1) ? Wk : (z == 2) ? Wv : Wo;
    int n0 = blockIdx.x * 32, k0 = blockIdx.y * 32;
    int tx = threadIdx.x, ty = threadIdx.y;
#pragma unroll
    for (int i = 0; i < 4; i++)
        t[ty + i * 8][tx] = W[(size_t)(k0 + ty + i * 8) * HID + n0 + tx];
    __syncthreads();
    __half* dst = g_wt + (size_t)z * HID * HID;
#pragma unroll
    for (int i = 0; i < 4; i++) {
        int n = n0 + ty + i * 8;
        float sc = (z == 3) ? 1.0f : g_mod[n] * ((z == 0) ? 0.125f : 1.0f);
        dst[(size_t)n * HID + k0 + tx] = __float2half_rn(t[tx][ty + i * 8] * sc);
    }
}

__global__ __launch_bounds__(256) void roll_t_kernel() {
    __shared__ __half ts[65][72];
    int n0 = blockIdx.x * 64, bh = blockIdx.y, tid = threadIdx.x;
    int rr = tid >> 2, seg = (tid & 3) * 16;
    const __half* src = g_v + ((size_t)bh * SQ + n0 + rr) * HD + seg;
    *(uint4*)&ts[rr][seg] = *(const uint4*)src;
    *(uint4*)&ts[rr][seg + 8] = *(const uint4*)(src + 8);
    if (tid < 4) {
        int nz = (n0 + 64) & (SQ - 1);
        const __half* s2 = g_v + ((size_t)bh * SQ + nz) * HD + tid * 16;
        *(uint4*)&ts[64][tid * 16] = *(const uint4*)s2;
        *(uint4*)&ts[64][tid * 16 + 8] = *(const uint4*)(s2 + 8);
    }
    __syncthreads();
    int d = tid >> 2, ns = (tid & 3) * 16;
    const float R = 0.7071067811865476f;
    __half2 ov[8];
#pragma unroll
    for (int i = 0; i < 8; i++) {
        int n = ns + 2 * i;
        float a = __half2float(ts[n][d]);
        float b = __half2float(ts[n + 1][d]);
        float c = __half2float(ts[n + 2][d]);
        ov[i] = __floats2half2_rn((a + b) * R, (b + c) * R);
    }
    __half* dst = g_vt + ((size_t)bh * HD + d) * SQ + n0 + ns;
    *(uint4*)dst = *(uint4*)&ov[0];
    *(uint4*)(dst + 8) = *(uint4*)&ov[4];
}

// ---------------------------------------------------------------- fp16 GEMM core v6
// 512 thr = 16 warps (4m x 4n), block 128x128, warp m32 x n32, kblock 32.
// 3-stage cp.async ring, prefetch distance 2, ONE sync per stage.
// Hazard-safe order: wait -> sync -> prefetch((st+2)%3) -> compute(st%3):
// the sync proves all threads finished stage st-1, whose buffer (st-1)%3 ==
// (st+2)%3 is the one the prefetch overwrites.
#define GLDA 40
#define GSTG (128*GLDA)

__device__ __forceinline__ void gemm_core(const __half* Arow0, const __half* Brow0,
                                          float (&acc)[2][4][4]) {
    extern __shared__ __half sm[];
    __half* As = sm;               // [3][128][40]
    __half* Bs = sm + 3 * GSTG;    // [3][128][40]
    int tid = threadIdx.x, lane = tid & 31, w = tid >> 5;
    int wm = w >> 2, wn = w & 3;
    int lrow = tid >> 2, lseg = (tid & 3) * 8;

    const __half* sa = Arow0 + (size_t)lrow * HID + lseg;
    const __half* sb = Brow0 + (size_t)lrow * HID + lseg;
    unsigned da = su(As + lrow * GLDA + lseg);
    unsigned db = su(Bs + lrow * GLDA + lseg);

    // prologue: stages 0,1 (one commit group each)
#pragma unroll
    for (int s = 0; s < 2; s++) {
        CP16(da + (unsigned)(s * GSTG * 2), sa + s * 32);
        CP16(db + (unsigned)(s * GSTG * 2), sb + s * 32);
        CPC();
    }

    int arow = wm * 32 + (lane & 15);
    int brow = wn * 32 + (lane & 15);
    int coff = (lane >> 4) * 8;

    for (int st = 0; st < 32; st++) {
        asm volatile("cp.async.wait_group 1;");
        __syncthreads();
        if (st + 2 < 32) {
            unsigned nb = (unsigned)((st + 2) % 3);
            CP16(da + nb * GSTG * 2, sa + (st + 2) * 32);
            CP16(db + nb * GSTG * 2, sb + (st + 2) * 32);
        }
        CPC();
        const __half* Ac = As + (st % 3) * GSTG;
        const __half* Bc = Bs + (st % 3) * GSTG;
#pragma unroll
        for (int kk = 0; kk < 2; kk++) {
            unsigned au[2][4], bu[2][4];
#pragma unroll
            for (int i = 0; i < 2; i++)
                LDSM4(au[i][0], au[i][1], au[i][2], au[i][3],
                      su(Ac + (arow + i * 16) * GLDA + kk * 16 + coff));
#pragma unroll
            for (int jp = 0; jp < 2; jp++)
                LDSM4(bu[jp][0], bu[jp][1], bu[jp][2], bu[jp][3],
                      su(Bc + (brow + jp * 16) * GLDA + kk * 16 + coff));
#pragma unroll
            for (int i = 0; i < 2; i++)
#pragma unroll
                for (int j = 0; j < 4; j++)
                    HMMA(acc[i][j], au[i][0], au[i][1], au[i][2], au[i][3],
                         bu[j >> 1][j & 1], bu[j >> 1][2 + (j & 1)]);
        }
    }
}

#define GS_BYTES (6*GSTG*2)

__global__ __launch_bounds__(512, 2) void qkv_gemm() {
    int mode = blockIdx.z;
    float acc[2][4][4];
#pragma unroll
    for (int i = 0; i < 2; i++)
#pragma unroll
        for (int j = 0; j < 4; j++)
#pragma unroll
            for (int e = 0; e < 4; e++) acc[i][j][e] = 0.f;
    int bm = blockIdx.y, bn = blockIdx.x;
    gemm_core(g_xh + (size_t)bm * 128 * HID,
              g_wt + (size_t)mode * HID * HID + (size_t)bn * 128 * HID, acc);

    __half* dst = (mode == 0) ? g_q : (mode == 1) ? g_k : g_v;
    int tid = threadIdx.x, lane = tid & 31, w = tid >> 5;
    int wm = w >> 2, wn = w & 3, r = lane >> 2, c = lane & 3;
#pragma unroll
    for (int i = 0; i < 2; i++) {
#pragma unroll
        for (int ro = 0; ro < 2; ro++) {
            int grow = bm * 128 + wm * 32 + i * 16 + r + ro * 8;
            int bb = grow >> 11, ss = grow & 2047;
#pragma unroll
            for (int j = 0; j < 4; j++) {
                int col = bn * 128 + wn * 32 + j * 8 + 2 * c;
                int hh = col >> 6, dd = col & 63;
                __half2 v = __floats2half2_rn(acc[i][j][ro * 2],
                                              acc[i][j][ro * 2 + 1]);
                *(__half2*)&dst[(((size_t)(bb * HEADS + hh) * SQ + ss) * HD + dd)] = v;
            }
        }
    }
}

__global__ __launch_bounds__(512, 2) void out_gemm(float* __restrict__ C) {
    float acc[2][4][4];
#pragma unroll
    for (int i = 0; i < 2; i++)
#pragma unroll
        for (int j = 0; j < 4; j++)
#pragma unroll
            for (int e = 0; e < 4; e++) acc[i][j][e] = 0.f;
    int bm = blockIdx.y, bn = blockIdx.x;
    gemm_core(g_att + (size_t)bm * 128 * HID,
              g_wt + (size_t)3 * HID * HID + (size_t)bn * 128 * HID, acc);

    int tid = threadIdx.x, lane = tid & 31, w = tid >> 5;
    int wm = w >> 2, wn = w & 3, r = lane >> 2, c = lane & 3;
#pragma unroll
    for (int i = 0; i < 2; i++) {
#pragma unroll
        for (int ro = 0; ro < 2; ro++) {
            int grow = bm * 128 + wm * 32 + i * 16 + r + ro * 8;
#pragma unroll
            for (int j = 0; j < 4; j++) {
                int col = bn * 128 + wn * 32 + j * 8 + 2 * c;
                float2 v = {acc[i][j][ro * 2], acc[i][j][ro * 2 + 1]};
                *(float2*)&C[(size_t)grow * HID + col] = v;
            }
        }
    }
}

// ---------------------------------------------------------------- flash attention fp16 (R14-proven)
// 8 warps, warp owns rows [w*16,w*16+16), N-tile 64, cp.async double-buffered,
// one sync per iteration.
#define AQ 0
#define AK (128*72)
#define AV (AK + 2*64*72)
#define ATRIG (AV + 2*64*72)
#define ATT_BYTES (ATRIG*2 + 2*128*4)

__global__ __launch_bounds__(256, 2) void attn_kernel() {
    extern __shared__ __half sma[];
    __half* Qs = sma + AQ;
    __half* Ks = sma + AK;
    __half* Vts = sma + AV;
    float* cjs = (float*)(sma + ATRIG);   // [2][64]
    float* sjs = cjs + 128;               // [2][64]

    int m0 = blockIdx.x * 128, h = blockIdx.y, b = blockIdx.z;
    int bh = b * HEADS + h;
    const __half* Qg = g_q + (size_t)bh * SQ * HD;
    const __half* Kg = g_k + (size_t)bh * SQ * HD;
    const __half* Vg = g_vt + (size_t)bh * HD * SQ;

    int tid = threadIdx.x, lane = tid & 31, w = tid >> 5;
    int r = lane >> 2, c = lane & 3;
    int krow = tid >> 2, kseg = (tid & 3) * 16;

    {   // Q tile -> smem
        int row = tid >> 1, seg = (tid & 1) * 32;
        const uint4* s = (const uint4*)(Qg + (size_t)(m0 + row) * HD + seg);
        uint4* d = (uint4*)(Qs + row * 72 + seg);
        d[0] = s[0]; d[1] = s[1]; d[2] = s[2]; d[3] = s[3];
    }
    // prologue: async load tile 0 into buffer 0
    {
        CP16(su(Ks + krow * 72 + kseg), Kg + (size_t)krow * HD + kseg);
        CP16(su(Ks + krow * 72 + kseg + 8), Kg + (size_t)krow * HD + kseg + 8);
        CP16(su(Vts + krow * 72 + kseg), Vg + (size_t)krow * SQ + kseg);
        CP16(su(Vts + krow * 72 + kseg + 8), Vg + (size_t)krow * SQ + kseg + 8);
        if (tid < 16) CP16(su(cjs + tid * 4), g_cs + tid * 4);
        else if (tid < 32) CP16(su(sjs + (tid - 16) * 4), g_sn + (tid - 16) * 4);
        CPC();
    }
    asm volatile("cp.async.wait_group 0;");
    __syncthreads();   // Q + buffer0 ready

    unsigned qa[4][4];
#pragma unroll
    for (int kk = 0; kk < 4; kk++)
        LDSM4(qa[kk][0], qa[kk][1], qa[kk][2], qa[kk][3],
              su(Qs + (w * 16 + (lane & 15)) * 72 + kk * 16 + (lane >> 4) * 8));

    float cm0, sm0, cm1, sm1;  // premultiplied by LOG2E
    {
        int row = m0 + w * 16 + r;
        cm0 = g_cs[row] * LOG2E; sm0 = g_sn[row] * LOG2E;
        cm1 = g_cs[row + 8] * LOG2E; sm1 = g_sn[row + 8] * LOG2E;
    }
    float l0 = 0.f, l1 = 0.f;
    float o[8][4];
#pragma unroll
    for (int j = 0; j < 8; j++)
#pragma unroll
        for (int e = 0; e < 4; e++) o[j][e] = 0.f;

    for (int it = 0; it < 32; it++) {
        int buf = it & 1;
        const __half* Kc = Ks + buf * 4608;
        const __half* Vc = Vts + buf * 4608;
        const float* cjb = cjs + buf * 64;
        const float* sjb = sjs + buf * 64;

        if (it < 31) {   // prefetch next tile into other buffer
            int nb = buf ^ 1;
            int n1 = (it + 1) * 64;
            CP16(su(Ks + nb * 4608 + krow * 72 + kseg), Kg + (size_t)(n1 + krow) * HD + kseg);
            CP16(su(Ks + nb * 4608 + krow * 72 + kseg + 8), Kg + (size_t)(n1 + krow) * HD + kseg + 8);
            CP16(su(Vts + nb * 4608 + krow * 72 + kseg), Vg + (size_t)krow * SQ + n1 + kseg);
            CP16(su(Vts + nb * 4608 + krow * 72 + kseg + 8), Vg + (size_t)krow * SQ + n1 + kseg + 8);
            if (tid < 16) CP16(su(cjs + nb * 64 + tid * 4), g_cs + n1 + tid * 4);
            else if (tid < 32) CP16(su(sjs + nb * 64 + (tid - 16) * 4), g_sn + n1 + (tid - 16) * 4);
            CPC();
        }

        // S = Q K^T (m16 x n64)
        float s[8][4];
#pragma unroll
        for (int j = 0; j < 8; j++)
#pragma unroll
            for (int e = 0; e < 4; e++) s[j][e] = 0.f;
#pragma unroll
        for (int kk = 0; kk < 4; kk++) {
#pragma unroll
            for (int jp = 0; jp < 4; jp++) {
                unsigned b0, b1, b2, b3;
                LDSM4(b0, b1, b2, b3,
                      su(Kc + (jp * 16 + (lane & 15)) * 72 + kk * 16 + (lane >> 4) * 8));
                HMMA(s[2 * jp], qa[kk][0], qa[kk][1], qa[kk][2], qa[kk][3], b0, b2);
                HMMA(s[2 * jp + 1], qa[kk][0], qa[kk][1], qa[kk][2], qa[kk][3], b1, b3);
            }
        }

        // interference + exp2(s - SHF) + l accumulation, pack to fp16 A-frags
        unsigned pf[4][4];
#pragma unroll
        for (int j = 0; j < 8; j++) {
            float2 cj = *(float2*)&cjb[j * 8 + 2 * c];
            float2 sj = *(float2*)&sjb[j * 8 + 2 * c];
            float w00 = cm0 * cj.x + sm0 * sj.x;
            float w01 = cm0 * cj.y + sm0 * sj.y;
            float w10 = cm1 * cj.x + sm1 * sj.x;
            float w11 = cm1 * cj.y + sm1 * sj.y;
            s[j][0] = ex2(fmaf(s[j][0], w00, -SHF));
            s[j][1] = ex2(fmaf(s[j][1], w01, -SHF));
            s[j][2] = ex2(fmaf(s[j][2], w10, -SHF));
            s[j][3] = ex2(fmaf(s[j][3], w11, -SHF));
            l0 += s[j][0] + s[j][1];
            l1 += s[j][2] + s[j][3];
        }
#pragma unroll
        for (int kk = 0; kk < 4; kk++) {
            pf[kk][0] = pk(s[2 * kk][0], s[2 * kk][1]);
            pf[kk][1] = pk(s[2 * kk][2], s[2 * kk][3]);
            pf[kk][2] = pk(s[2 * kk + 1][0], s[2 * kk + 1][1]);
            pf[kk][3] = pk(s[2 * kk + 1][2], s[2 * kk + 1][3]);
        }

        // O += P @ V' (m16 x d64, k=n64)
#pragma unroll
        for (int kk = 0; kk < 4; kk++) {
#pragma unroll
            for (int jp = 0; jp < 4; jp++) {
                unsigned b0, b1, b2, b3;
                LDSM4(b0, b1, b2, b3,
                      su(Vc + (jp * 16 + (lane & 15)) * 72 + kk * 16 + (lane >> 4) * 8));
                HMMA(o[2 * jp], pf[kk][0], pf[kk][1], pf[kk][2], pf[kk][3], b0, b2);
                HMMA(o[2 * jp + 1], pf[kk][0], pf[kk][1], pf[kk][2], pf[kk][3], b1, b3);
            }
        }

        if (it < 31) {   // next buffer ready + all warps done with it
            asm volatile("cp.async.wait_group 0;");
            __syncthreads();
        }
    }

    l0 += __shfl_xor_sync(0xffffffffu, l0, 1);
    l0 += __shfl_xor_sync(0xffffffffu, l0, 2);
    l1 += __shfl_xor_sync(0xffffffffu, l1, 1);
    l1 += __shfl_xor_sync(0xffffffffu, l1, 2);
    float i0 = 1.0f / l0, i1 = 1.0f / l1;

    int row0 = b * SQ + m0 + w * 16 + r;
#pragma unroll
    for (int j = 0; j < 8; j++) {
        int col = h * HD + j * 8 + 2 * c;
        *(__half2*)&g_att[(size_t)row0 * HID + col] =
            __floats2half2_rn(o[j][0] * i0, o[j][1] * i0);
        *(__half2*)&g_att[(size_t)(row0 + 8) * HID + col] =
            __floats2half2_rn(o[j][2] * i1, o[j][3] * i1);
    }
}

// ---------------------------------------------------------------- launch
extern "C" void kernel_launch(void* const* d_in, const int* in_sizes, int n_in,
                              void* d_out, int out_size) {
    const float* x     = (const float*)d_in[0];
    const float* Wq    = (const float*)d_in[1];
    const float* Wk    = (const float*)d_in[2];
    const float* Wv    = (const float*)d_in[3];
    const float* Wo    = (const float*)d_in[4];
    const float* phase = (const float*)d_in[5];
    const float* amp   = (const float*)d_in[6];
    float* out = (float*)d_out;

    cudaFuncSetAttribute(qkv_gemm, cudaFuncAttributeMaxDynamicSharedMemorySize, GS_BYTES);
    cudaFuncSetAttribute(out_gemm, cudaFuncAttributeMaxDynamicSharedMemorySize, GS_BYTES);
    cudaFuncSetAttribute(attn_kernel, cudaFuncAttributeMaxDynamicSharedMemorySize, ATT_BYTES);

    prep_kernel<<<8, 256>>>(phase, amp);
    convert_x<<<ROWS_TOT * HID / (256 * 8), 256>>>(x);
    transpose_w<<<dim3(32, 32, 4), dim3(32, 8)>>>(Wq, Wk, Wv, Wo);
    qkv_gemm<<<dim3(8, 32, 3), 512, GS_BYTES>>>();
    roll_t_kernel<<<dim3(SQ / 64, BH), 256>>>();
    attn_kernel<<<dim3(16, 16, 2), 256, ATT_BYTES>>>();
    out_gemm<<<dim3(8, 32), 512, GS_BYTES>>>(out);
}